// round 10
// baseline (speedup 1.0000x reference)
#include <cuda_runtime.h>
#include <cuda_fp16.h>
#include <cstdint>

// SGConv K=2: h = P (P x), P = D^-1/2 (A + I) D^-1/2, deg over dst (+ self loop).
// z = dis .* h form: out[d] = dis[d]*(z[d] + sum_{s in N(d)} z[s]); CSR stores only
// src. z kept in fp16, one contiguous 192B row per node (24 uint2).
// Hop profile (R7): issue=63%, occ=80% -> mixed issue/L2-latency regime.
// This round: 8-edge unroll (8 LDG.64 in flight per warp) to hide the ~260cyc
// L2 gather latency; arithmetic unchanged (fp32 accumulate, bit-identical).
// Launches: memset, degree(+rank), scan(prefix+dis), scatter(+z0 scale), hop1, hop2.

#define N_NODES 50000
#define N_EDGES 800000
#define N_FEAT  96
#define ROW_U   48                            // u32 per fp16 row
#define ROW_V   24                            // uint2 per fp16 row
#define SCAN_B  1024
#define N_CHUNK ((N_NODES + SCAN_B - 1) / SCAN_B)   // 49

// ---------------- device scratch (allocation-free rule: __device__ globals) ----
__device__ int   g_counts[N_NODES];           // in-degree (dst)
__device__ int   g_rowptr[N_NODES + 1];       // CSR row pointers (by dst)
__device__ float g_dis[N_NODES];              // (deg+1)^-1/2
__device__ int   g_pos[N_EDGES];              // within-row rank of edge e
__device__ int   g_col[N_EDGES];              // src per CSR slot
__device__ __align__(128) uint2 g_z0h[(size_t)N_NODES * ROW_V];
__device__ __align__(128) uint2 g_z1h[(size_t)N_NODES * ROW_V];

// ---------------- per-warp dtype detection -------------------------------------
// Odd 32-bit words of src (int64 view) are all 0 iff int64 (values < 50000).
// For int32 data those words are src values: P(32 consecutive all zero) ~ 0.
__device__ __forceinline__ bool warp_is64(const void* ei, int ebase, int lane) {
    int e = ebase + lane;
    if (e >= N_EDGES) e = N_EDGES - 1;
    unsigned int v = ((const unsigned int*)ei)[2 * e + 1];
    return __all_sync(0xFFFFFFFFu, v == 0);
}
__device__ __forceinline__ int edge_src(const void* ei, int e, bool is64) {
    return is64 ? (int)((const long long*)ei)[e] : ((const int*)ei)[e];
}
__device__ __forceinline__ int edge_dst(const void* ei, int e, bool is64) {
    return is64 ? (int)((const long long*)ei)[N_EDGES + e]
                : ((const int*)ei)[N_EDGES + e];
}

// ---------------- degree + edge rank -------------------------------------------
__global__ void degree_kernel(const void* __restrict__ ei) {
    int e = blockIdx.x * blockDim.x + threadIdx.x;
    if (e >= N_EDGES) return;
    const int lane = threadIdx.x & 31;
    bool is64 = warp_is64(ei, e - lane, lane);
    int d = edge_dst(ei, e, is64);
    g_pos[e] = atomicAdd(&g_counts[d], 1);
}

// ---------------- single-kernel scan: prefix + dis + rowptr ---------------------
__global__ void __launch_bounds__(SCAN_B) scan_kernel() {
    const int tid = threadIdx.x, lane = tid & 31, wid = tid >> 5;
    const int b = blockIdx.x;
    const int i = b * SCAN_B + tid;

    __shared__ int wred[32];
    __shared__ int s_pre;
    __shared__ int wscan[32];

    // prefix over chunks [0, b)
    int pre = 0;
    const int lim = b * SCAN_B;
    for (int j = tid; j < lim; j += SCAN_B) pre += g_counts[j];
    int v = pre;
    #pragma unroll
    for (int off = 16; off > 0; off >>= 1) v += __shfl_down_sync(0xFFFFFFFFu, v, off);
    if (lane == 0) wred[wid] = v;
    __syncthreads();
    if (wid == 0) {
        int s = wred[lane];
        #pragma unroll
        for (int off = 16; off > 0; off >>= 1) s += __shfl_down_sync(0xFFFFFFFFu, s, off);
        if (lane == 0) s_pre = s;
    }

    int c = 0;
    if (i < N_NODES) {
        c = g_counts[i];
        g_dis[i] = rsqrtf((float)(c + 1));   // +1 self loop
    }
    int incl = c;
    #pragma unroll
    for (int off = 1; off < 32; off <<= 1) {
        int t = __shfl_up_sync(0xFFFFFFFFu, incl, off);
        if (lane >= off) incl += t;
    }
    if (lane == 31) wscan[wid] = incl;
    __syncthreads();
    if (wid == 0) {
        int s = wscan[lane];
        #pragma unroll
        for (int off = 1; off < 32; off <<= 1) {
            int t = __shfl_up_sync(0xFFFFFFFFu, s, off);
            if (lane >= off) s += t;
        }
        wscan[lane] = s;
    }
    __syncthreads();

    if (i < N_NODES)
        g_rowptr[i + 1] = s_pre + (wid > 0 ? wscan[wid - 1] : 0) + incl;
    if (b == 0 && tid == 0) g_rowptr[0] = 0;
}

// ---------------- scatter (atomic-free) + z0 scale ------------------------------
__global__ void __launch_bounds__(256) scatter_scale_kernel(const void* __restrict__ ei,
                                                            const float* __restrict__ x) {
    int idx = blockIdx.x * blockDim.x + threadIdx.x;
    const int lane = threadIdx.x & 31;

    if (idx < N_EDGES) {   // N_EDGES % 32 == 0: whole warps take this branch
        bool is64 = warp_is64(ei, idx - lane, lane);
        int s = edge_src(ei, idx, is64);
        int d = edge_dst(ei, idx, is64);
        g_col[g_rowptr[d] + g_pos[idx]] = s;
    }

    // z0 = half(dis .* x): one u32 (half2) per iteration, grid-stride.
    const int TOT = N_NODES * ROW_U;
    const int stride = gridDim.x * blockDim.x;
    unsigned int* z0 = (unsigned int*)g_z0h;
    for (int i = idx; i < TOT; i += stride) {
        int node = i / ROW_U;
        float sdis = g_dis[node];
        float2 v = ((const float2*)x)[i];
        __half2 h = __floats2half2_rn(sdis * v.x, sdis * v.y);
        z0[i] = *(unsigned int*)&h;
    }
}

// decode-accumulate helper: uint2 of 4 halves -> 4 fp32 accumulators
#define ACC_U2(v)                                               \
    do {                                                        \
        float2 _t;                                              \
        _t = __half22float2(*(__half2*)&(v).x);                 \
        a0 += _t.x; a1 += _t.y;                                 \
        _t = __half22float2(*(__half2*)&(v).y);                 \
        a2 += _t.x; a3 += _t.y;                                 \
    } while (0)

// ---------------- hop: warp/node, 8-deep LDG.64 pipeline, fp32 accumulate -------
// Lane L (<24) owns features 4L..4L+3 via uint2. int32 index math only.
// FIRST: z-space fp16 out (*dis^2); else final fp32 out (*dis).
template <bool FIRST>
__global__ void __launch_bounds__(256) hop_kernel(const uint2* __restrict__ zin,
                                                  uint2* __restrict__ zout,
                                                  float4* __restrict__ fout) {
    const int node = blockIdx.x * (blockDim.x >> 5) + (threadIdx.x >> 5);
    if (node >= N_NODES) return;
    const int lane = threadIdx.x & 31;
    const bool act = (lane < ROW_V);

    float a0 = 0.f, a1 = 0.f, a2 = 0.f, a3 = 0.f;
    if (act) {
        uint2 u = zin[node * ROW_V + lane];
        ACC_U2(u);
    }

    int e = g_rowptr[node];
    const int end = g_rowptr[node + 1];

    // 8-edge pipeline: all col loads, then all addresses, then all gathers
    // issued back-to-back (8 LDG.64 in flight), then decode+accumulate.
    for (; e + 7 < end; e += 8) {
        int c0 = g_col[e],     c1 = g_col[e + 1];
        int c2 = g_col[e + 2], c3 = g_col[e + 3];
        int c4 = g_col[e + 4], c5 = g_col[e + 5];
        int c6 = g_col[e + 6], c7 = g_col[e + 7];
        int i0 = c0 * ROW_V + lane, i1 = c1 * ROW_V + lane;
        int i2 = c2 * ROW_V + lane, i3 = c3 * ROW_V + lane;
        int i4 = c4 * ROW_V + lane, i5 = c5 * ROW_V + lane;
        int i6 = c6 * ROW_V + lane, i7 = c7 * ROW_V + lane;
        if (act) {
            uint2 v0 = zin[i0];
            uint2 v1 = zin[i1];
            uint2 v2 = zin[i2];
            uint2 v3 = zin[i3];
            uint2 v4 = zin[i4];
            uint2 v5 = zin[i5];
            uint2 v6 = zin[i6];
            uint2 v7 = zin[i7];
            ACC_U2(v0); ACC_U2(v1); ACC_U2(v2); ACC_U2(v3);
            ACC_U2(v4); ACC_U2(v5); ACC_U2(v6); ACC_U2(v7);
        }
    }
    for (; e + 3 < end; e += 4) {
        int c0 = g_col[e],     c1 = g_col[e + 1];
        int c2 = g_col[e + 2], c3 = g_col[e + 3];
        int i0 = c0 * ROW_V + lane, i1 = c1 * ROW_V + lane;
        int i2 = c2 * ROW_V + lane, i3 = c3 * ROW_V + lane;
        if (act) {
            uint2 v0 = zin[i0];
            uint2 v1 = zin[i1];
            uint2 v2 = zin[i2];
            uint2 v3 = zin[i3];
            ACC_U2(v0); ACC_U2(v1); ACC_U2(v2); ACC_U2(v3);
        }
    }
    for (; e < end; e++) {
        int i = g_col[e] * ROW_V + lane;
        if (act) {
            uint2 v = zin[i];
            ACC_U2(v);
        }
    }

    float sc = g_dis[node];
    if (FIRST) {
        sc = sc * sc;
        if (act) {
            __half2 h01 = __floats2half2_rn(sc * a0, sc * a1);
            __half2 h23 = __floats2half2_rn(sc * a2, sc * a3);
            uint2 o;
            o.x = *(unsigned int*)&h01;
            o.y = *(unsigned int*)&h23;
            zout[node * ROW_V + lane] = o;
        }
    } else {
        if (act)
            fout[node * ROW_V + lane] =
                make_float4(sc * a0, sc * a1, sc * a2, sc * a3);
    }
}

// ---------------- launch --------------------------------------------------------
extern "C" void kernel_launch(void* const* d_in, const int* in_sizes, int n_in,
                              void* d_out, int out_size) {
    const float* x  = (const float*)d_in[0];
    const void*  ei = d_in[1];

    int* cnt = nullptr; uint2 *z0, *z1;
    cudaGetSymbolAddress((void**)&cnt, g_counts);
    cudaGetSymbolAddress((void**)&z0, g_z0h);
    cudaGetSymbolAddress((void**)&z1, g_z1h);

    const int TB = 256;
    cudaMemsetAsync(cnt, 0, N_NODES * sizeof(int));
    degree_kernel<<<N_EDGES / TB, TB>>>(ei);
    scan_kernel<<<N_CHUNK, SCAN_B>>>();
    const int TOT = N_NODES * ROW_U;
    scatter_scale_kernel<<<(TOT + TB - 1) / TB, TB>>>(ei, x);

    const int warps_per_block = TB / 32;
    const int hop_grid = (N_NODES + warps_per_block - 1) / warps_per_block;
    hop_kernel<true ><<<hop_grid, TB>>>(z0, z1, nullptr);
    hop_kernel<false><<<hop_grid, TB>>>(z1, nullptr, (float4*)d_out);
}